// round 17
// baseline (speedup 1.0000x reference)
#include <cuda_runtime.h>
#include <math.h>

#define BETA 0.1f

// FINAL — best measured configuration over a 15-round lever matrix.
// One block per (b,p) tile, 256 threads, de-interleaved store phase:
//   warps 0-3 (tid 0..127)  -> entire 16 KB `places` tile
//   warps 4-7 (tid 128..255)-> entire 16 KB `sampled` tile
// 1024 float4 per half-block in 8 coalesced iterations, plain STG.128,
// default cache policy. Kernel sits at the effective HBM3e write-stream
// roofline (~5.15 TB/s sustained, 97%-write traffic); store width/path,
// L2 policy, grid shape, burst length, and dependency decoupling all
// measured neutral (41.6-43.0us band).
__global__ __launch_bounds__(256, 8)
void spatial_sampler_kernel(const float* __restrict__ x_cat,
                            const float* __restrict__ noise,
                            float* __restrict__ out,
                            long long half_elems)
{
    __shared__ float sx[128];   // [0:64) h row, [64:128) v row
    __shared__ float ss[128];   // masked rows (h part pre-scaled by 100)
    __shared__ float wmax[4];

    const int bp  = blockIdx.x;
    const int tid = threadIdx.x;

    const float* xrow = x_cat + (long long)bp * 128;
    const float* nrow = noise + (long long)bp * 128;

    // --- load + log_pdf + per-row max (each 64-wide row = 2 warps) ---
    float lp = -INFINITY;
    float xv = 0.f;
    if (tid < 128) {
        xv = xrow[tid];
        lp = logf(xv) + BETA * nrow[tid];
        sx[tid] = xv;
    }
    float m = lp;
    #pragma unroll
    for (int off = 16; off > 0; off >>= 1)
        m = fmaxf(m, __shfl_xor_sync(0xffffffffu, m, off));
    if (tid < 128 && (tid & 31) == 0)
        wmax[tid >> 5] = m;
    __syncthreads();

    if (tid < 128) {
        float rowmax = (tid < 64) ? fmaxf(wmax[0], wmax[1])
                                  : fmaxf(wmax[2], wmax[3]);
        float s = (lp == rowmax) ? xv : 0.f;
        ss[tid] = (tid < 64) ? s * 100.0f : s;   // fold *100 into h half
    }
    __syncthreads();

    // --- de-interleaved stores: half-block per output tensor ---
    const int  half_tid = tid & 127;          // 0..127 within half-block
    const bool is_samp  = (tid >= 128);

    const float* hsrc = is_samp ? ss      : sx;
    const float4* v4  = reinterpret_cast<const float4*>(is_samp ? &ss[64] : &sx[64]);
    float4* dst = reinterpret_cast<float4*>(
        out + (is_samp ? half_elems : 0) + (long long)bp * 4096);

    #pragma unroll
    for (int it = 0; it < 8; ++it) {
        const int i  = half_tid + it * 128;   // float4 index 0..1023
        const int j  = i >> 4;                // row 0..63
        const int c4 = i & 15;                // float4 col 0..15

        const float hj = hsrc[j];
        float4 vv = v4[c4];
        float4 o;
        o.x = hj * vv.x; o.y = hj * vv.y; o.z = hj * vv.z; o.w = hj * vv.w;
        dst[i] = o;
    }
}

extern "C" void kernel_launch(void* const* d_in, const int* in_sizes, int n_in,
                              void* d_out, int out_size)
{
    const float* x_cat = (const float*)d_in[0];
    const float* noise = (const float*)d_in[1];
    float* out = (float*)d_out;

    const long long half = (long long)out_size / 2;
    const int tiles = in_sizes[0] / 128;   // 8192 (b,p) tiles

    spatial_sampler_kernel<<<tiles, 256>>>(x_cat, noise, out, half);
}